// round 10
// baseline (speedup 1.0000x reference)
#include <cuda_runtime.h>
#include <cstdint>

// CSPN propagation:
//   out[b,0,y,x] = sum_{t=0..24} gw[b,t,y+2,x+2] * src_t(y+2-t/5, x+2-t%5)
// src_t = h0 for t==12 (center) else hn; zero outside [0,H)x[0,W).
// gw (4,25,356,1220) f32, hn/h0 (4,1,352,1216) f32, out (4,1,352,1216) f32.
//
// Barrier-free cp.async weight pipeline: each lane prefetches exactly the
// 16 weight bytes (gw offsets x+2..x+5, 8B-aligned) it will itself consume,
// into a per-thread 8-slot smem ring. Consumption only needs the issuing
// thread's own cp.async.wait_group -> no __syncthreads anywhere.

#define K 5
#define Hc 352
#define Wc 1216
#define Hp 356
#define Wp 1220
#define Bc 4
#define NW 10                        // warps per block
#define NT (NW * 32)                 // 320 threads
#define NSTAGE 8                     // ring slots (pipeline depth 7)

__device__ __forceinline__ uint32_t smem_u32(const void* p) {
    uint32_t a;
    asm("{.reg .u64 t; cvta.to.shared.u64 t, %1; cvt.u32.u64 %0, t;}"
        : "=r"(a) : "l"(p));
    return a;
}

__global__ __launch_bounds__(NT)
void cspn_kernel(const float* __restrict__ gw,
                 const float* __restrict__ hn,
                 const float* __restrict__ h0,
                 float* __restrict__ out)
{
    // [warp][slot][lane] : 16 B per lane per slot = 40960 B total
    __shared__ float2 wbuf[NW][NSTAGE][64];

    const int tid  = threadIdx.x;
    const int wid  = tid >> 5;
    const int lane = tid & 31;
    const int row  = blockIdx.x;             // (b, y)
    const int y    = row % Hc;
    const int b    = row / Hc;

    const int x = (wid << 7) + (lane << 2);  // 4 pixels at x..x+3, x % 4 == 0
    const bool active = (x < Wc);            // warp 9 lanes 16..31 idle

    const size_t PLANE = (size_t)Hp * Wp;    // 434320
    const float* wrow = gw + (size_t)b * 25 * PLANE + (size_t)(y + 2) * Wp;
    const float* hb   = hn + (size_t)b * Hc * Wc;
    const float* h0b  = h0 + (size_t)b * Hc * Wc;

    // per-thread smem ring base: 16 B per lane per slot
    const uint32_t dst0 = smem_u32(&wbuf[wid][0][0]) + (uint32_t)(lane * 16);

    // issue tap t: two 8B cp.async of gw offsets [x+2 .. x+5]
    auto issue = [&](int t) {
        if (active) {
            const float* src = wrow + (size_t)t * PLANE + (x + 2); // 8B aligned
            const uint32_t dst = dst0 + (uint32_t)((t & (NSTAGE - 1)) * 512);
            asm volatile("cp.async.ca.shared.global [%0], [%1], 8;"
                         :: "r"(dst), "l"(src));
            asm volatile("cp.async.ca.shared.global [%0], [%1], 8;"
                         :: "r"(dst + 8), "l"(src + 2));
        }
    };

    // prologue: taps 0..6 in flight (7 groups)
    #pragma unroll
    for (int t = 0; t < 7; ++t) {
        issue(t);
        asm volatile("cp.async.commit_group;");
    }

    float acc0 = 0.f, acc1 = 0.f, acc2 = 0.f, acc3 = 0.f;
    float4 c4 = make_float4(0.f, 0.f, 0.f, 0.f);
    if (active)
        c4 = __ldg(reinterpret_cast<const float4*>(h0b + (size_t)y * Wc + x)); // 16B aligned

    float v[8];

    #pragma unroll
    for (int t = 0; t < 25; ++t) {
        const int dy = t / K;
        const int dx = t % K;

        // refresh hn span [x-2, x+5] at each new tap row
        if (dx == 0) {
            const int iy = y + 2 - dy;
            const bool yok = (unsigned)iy < (unsigned)Hc;
            const float* rp = hb + (size_t)iy * Wc;
            #pragma unroll
            for (int k = 0; k < 8; ++k) {
                const int ix = x - 2 + k;
                v[k] = (active && yok && (unsigned)ix < (unsigned)Wc)
                         ? __ldg(rp + ix) : 0.f;
            }
        }

        // keep the pipeline full, then wait for tap t's group
        issue(t + 7);                        // no-op inside guard when t+7 > 24
        asm volatile("cp.async.commit_group;");
        asm volatile("cp.async.wait_group 7;");

        if (active) {
            const float2* slot = &wbuf[wid][t & (NSTAGE - 1)][lane * 2];
            const float2 wA = slot[0];       // gw[x+2], gw[x+3]
            const float2 wB = slot[1];       // gw[x+4], gw[x+5]

            float s0, s1, s2, s3;
            if (t == 12) {                   // center tap -> h0
                s0 = c4.x; s1 = c4.y; s2 = c4.z; s3 = c4.w;
            } else {
                const int base = 4 - dx;
                s0 = v[base + 0]; s1 = v[base + 1];
                s2 = v[base + 2]; s3 = v[base + 3];
            }
            acc0 = fmaf(wA.x, s0, acc0);
            acc1 = fmaf(wA.y, s1, acc1);
            acc2 = fmaf(wB.x, s2, acc2);
            acc3 = fmaf(wB.y, s3, acc3);
        }
    }

    if (active) {
        float4 o = make_float4(acc0, acc1, acc2, acc3);
        *reinterpret_cast<float4*>(out + (size_t)b * Hc * Wc + (size_t)y * Wc + x) = o;
    }
}

extern "C" void kernel_launch(void* const* d_in, const int* in_sizes, int n_in,
                              void* d_out, int out_size)
{
    const float* gw = (const float*)d_in[0];
    const float* hn = (const float*)d_in[1];
    const float* h0 = (const float*)d_in[2];
    float* out = (float*)d_out;

    cspn_kernel<<<Bc * Hc, NT>>>(gw, hn, h0, out);   // 1408 blocks
}